// round 10
// baseline (speedup 1.0000x reference)
#include <cuda_runtime.h>
#include <math.h>

// ProbabilisticMap: out[b][x][y][t] = N((x,y); mean(b,t), cov(b,t)) for a
// Bezier mixture of 8 control-point Gaussians.
// Shapes: cp_means (8,128,2), cp_covariances (8,128,2,2), out (128,64,64,50) fp32.
//
// R9: double-buffered TMA drain.
//   Block = one batch b x 256 pixels = 4 chunks of 64 px. Two 12.8 KB tile
//   buffers; while the async engine drains chunk c, warps compute chunk c+1.
//   Only ONE blocking wait_group.read 0 per CTA (amortized over 4 chunks),
//   vs one per CTA-worth-of-one-chunk in R8. Phase-0 params amortized 2x.

#define MAP_W 64
#define MAP_H 64
#define MAP_T 50
#define NUM_CP 8
#define BATCH 128

#define TPB 256
#define CHUNK_PX 64
#define N_CHUNKS 4
#define PX_PER_BLOCK (CHUNK_PX * N_CHUNKS)          // 256
#define CHUNK_FLOATS (CHUNK_PX * MAP_T)             // 3200
#define CHUNK_BYTES  (CHUNK_FLOATS * 4)             // 12800
#define BLOCKS_PER_B ((MAP_W * MAP_H) / PX_PER_BLOCK)   // 16
#define NUM_BLOCKS   (BATCH * BLOCKS_PER_B)         // 2048

__device__ __forceinline__ float ex2(float x) {
    float r;
    asm("ex2.approx.ftz.f32 %0, %1;" : "=f"(r) : "f"(x));
    return r;
}

__device__ __forceinline__ unsigned smem_u32(const void* p) {
    unsigned a;
    asm("{ .reg .u64 t; cvta.to.shared.u64 t, %1; cvt.u32.u64 %0, t; }"
        : "=r"(a) : "l"(p));
    return a;
}

__global__ __launch_bounds__(TPB)
void probmap_kernel(const float* __restrict__ cp_means,
                    const float* __restrict__ cp_covs,
                    float* __restrict__ out)
{
    __shared__ float4 sP4[MAP_T];                    // (mx, my, c0, c1)
    __shared__ float2 sP2[MAP_T];                    // (c2, ls)
    __shared__ __align__(16) float tile[2][CHUNK_FLOATS];  // 2 x 12.8 KB, output layout

    const int tid = threadIdx.x;
    const int b   = blockIdx.x >> 4;                 // 16 blocks per batch
    const int p0  = (blockIdx.x & 15) * PX_PER_BLOCK;

    // ---- Phase 0: per-t parameters (threads 192..241) ----
    const int tp = tid - 192;
    if ((unsigned)tp < (unsigned)MAP_T) {
        const float tt = (float)tp * (1.0f / (float)(MAP_T - 1));
        const float u  = 1.0f - tt;
        const float C[NUM_CP] = {1.f, 7.f, 21.f, 35.f, 35.f, 21.f, 7.f, 1.f};

        float up[NUM_CP];
        up[0] = 1.0f;
#pragma unroll
        for (int i = 1; i < NUM_CP; i++) up[i] = up[i - 1] * u;

        float mx = 0.f, my = 0.f;
        float ca = 0.f, cb = 0.f, cc = 0.f, cd = 0.f;
        float t_pow = 1.0f;
#pragma unroll
        for (int i = 0; i < NUM_CP; i++) {
            const float bas = C[i] * t_pow * up[NUM_CP - 1 - i];
            t_pow *= tt;
            const float b2 = bas * bas;
            const float* m  = cp_means + (i * BATCH + b) * 2;   // warp-broadcast LDG
            const float* cv = cp_covs  + (i * BATCH + b) * 4;
            mx = fmaf(bas, m[0], mx);
            my = fmaf(bas, m[1], my);
            ca = fmaf(b2, cv[0], ca);
            cb = fmaf(b2, cv[1], cb);
            cc = fmaf(b2, cv[2], cc);
            cd = fmaf(b2, cv[3], cd);
        }
        const float det     = ca * cd - cb * cc;
        const float inv_det = 1.0f / det;
        const float HL2E    = 0.5f * 1.4426950408889634f;      // 0.5*log2(e)
        // exponent-space: out = exp2(c0*dx^2 + c1*dx*dy + c2*dy^2 + ls)
        const float c0 = -HL2E * cd * inv_det;
        const float c1 =  HL2E * (cb + cc) * inv_det;
        const float c2 = -HL2E * ca * inv_det;
        const float ls = -0.5f * __log2f(39.478417604357434f * det);
        sP4[tp] = make_float4(mx, my, c0, c1);
        sP2[tp] = make_float2(c2, ls);
    }
    __syncthreads();

    const int w = tid >> 5;
    const int l = tid & 31;
    float* const out_base = out + (size_t)b * (MAP_W * MAP_H * MAP_T) + (size_t)p0 * MAP_T;

    for (int c = 0; c < N_CHUNKS; c++) {
        float* buf = tile[c & 1];

        // Reuse-safety: buffer (c-2) must be fully read by the engine.
        if (c >= 2) {
            if (tid == 0)
                asm volatile("cp.async.bulk.wait_group.read 1;" ::: "memory");
            __syncthreads();
        }

        // ---- compute chunk c: 64 pixels x 50 t, warp-uniform t ----
        const int cp0 = p0 + c * CHUNK_PX;
        const int pA = cp0 + l;
        const int pB = cp0 + l + 32;
        const float xA = (float)(pA >> 6), yA = (float)(pA & 63);
        const float xB = (float)(pB >> 6), yB = (float)(pB & 63);

        for (int t = w; t < MAP_T; t += 8) {
            const float4 q4 = sP4[t];                // broadcast LDS
            const float2 q2 = sP2[t];

            const float dxA = xA - q4.x, dyA = yA - q4.y;
            float sA = fmaf(q4.w, dyA, q4.z * dxA);
            sA = fmaf(sA, dxA, q2.y);
            sA = fmaf(q2.x * dyA, dyA, sA);
            buf[l * MAP_T + t] = ex2(sA);            // STS.32 (2-way conflict)

            const float dxB = xB - q4.x, dyB = yB - q4.y;
            float sB = fmaf(q4.w, dyB, q4.z * dxB);
            sB = fmaf(sB, dxB, q2.y);
            sB = fmaf(q2.x * dyB, dyB, sB);
            buf[(l + 32) * MAP_T + t] = ex2(sB);
        }
        __syncthreads();

        // ---- issue async drain of chunk c (overlaps with chunk c+1 compute) ----
        if (tid == 0) {
            asm volatile("fence.proxy.async;" ::: "memory");
            char* gdst = (char*)(out_base + (size_t)c * CHUNK_FLOATS);
            const unsigned ssrc = smem_u32(buf);
            asm volatile(
                "cp.async.bulk.global.shared::cta.bulk_group [%0], [%1], %2;"
                :: "l"(gdst), "r"(ssrc), "r"((unsigned)CHUNK_BYTES) : "memory");
            asm volatile("cp.async.bulk.commit_group;" ::: "memory");
        }
    }

    // Final: SMEM must not be released until the engine finishes reading.
    if (tid == 0)
        asm volatile("cp.async.bulk.wait_group.read 0;" ::: "memory");
}

extern "C" void kernel_launch(void* const* d_in, const int* in_sizes, int n_in,
                              void* d_out, int out_size)
{
    const float* cp_means = (const float*)d_in[0];  // (8,128,2)
    const float* cp_covs  = (const float*)d_in[1];  // (8,128,2,2)
    float* out = (float*)d_out;                     // (128,64,64,50)
    (void)in_sizes; (void)n_in; (void)out_size;

    probmap_kernel<<<NUM_BLOCKS, TPB>>>(cp_means, cp_covs, out);
}

// round 11
// speedup vs baseline: 1.0390x; 1.0390x over previous
#include <cuda_runtime.h>
#include <math.h>

// ProbabilisticMap: out[b][x][y][t] = N((x,y); mean(b,t), cov(b,t)) for a
// Bezier mixture of 8 control-point Gaussians.
// Shapes: cp_means (8,128,2), cp_covariances (8,128,2,2), out (128,64,64,50) fp32.
//
// R10: quadratic-in-y Horner hot loop.
//   For fixed (t,x) the exponent is s(y) = c2*y^2 + B'*y + C' (B',C' from
//   warp-uniform setup). Lanes = y values -> per element just 2 FMA + EX2 + STS.
//   Block = one b x 8 consecutive x; chunk = one x (64y x 50t = 12.8 KB,
//   contiguous in output), double-buffered cp.async.bulk drain.

#define MAP_W 64
#define MAP_H 64
#define MAP_T 50
#define NUM_CP 8
#define BATCH 128

#define TPB 256
#define X_PER_BLOCK 8
#define CHUNK_FLOATS (MAP_H * MAP_T)                // 3200 (one x slice)
#define CHUNK_BYTES  (CHUNK_FLOATS * 4)             // 12800
#define BLOCKS_PER_B (MAP_W / X_PER_BLOCK)          // 8
#define NUM_BLOCKS   (BATCH * BLOCKS_PER_B)         // 1024

__device__ __forceinline__ float ex2(float x) {
    float r;
    asm("ex2.approx.ftz.f32 %0, %1;" : "=f"(r) : "f"(x));
    return r;
}

__device__ __forceinline__ unsigned smem_u32(const void* p) {
    unsigned a;
    asm("{ .reg .u64 t; cvta.to.shared.u64 t, %1; cvt.u32.u64 %0, t; }"
        : "=r"(a) : "l"(p));
    return a;
}

__global__ __launch_bounds__(TPB)
void probmap_kernel(const float* __restrict__ cp_means,
                    const float* __restrict__ cp_covs,
                    float* __restrict__ out)
{
    __shared__ float4 sP4[MAP_T];                    // (mx, my, c0, c1)
    __shared__ float2 sP2[MAP_T];                    // (c2, ls)
    __shared__ __align__(16) float tile[2][CHUNK_FLOATS];  // 2 x 12.8 KB

    const int tid = threadIdx.x;
    const int b   = blockIdx.x >> 3;                 // 8 blocks per batch
    const int x0  = (blockIdx.x & 7) * X_PER_BLOCK;  // first x of this block

    // ---- Phase 0: per-t parameters (threads 192..241) ----
    const int tp = tid - 192;
    if ((unsigned)tp < (unsigned)MAP_T) {
        const float tt = (float)tp * (1.0f / (float)(MAP_T - 1));
        const float u  = 1.0f - tt;
        const float C[NUM_CP] = {1.f, 7.f, 21.f, 35.f, 35.f, 21.f, 7.f, 1.f};

        float up[NUM_CP];
        up[0] = 1.0f;
#pragma unroll
        for (int i = 1; i < NUM_CP; i++) up[i] = up[i - 1] * u;

        float mx = 0.f, my = 0.f;
        float ca = 0.f, cb = 0.f, cc = 0.f, cd = 0.f;
        float t_pow = 1.0f;
#pragma unroll
        for (int i = 0; i < NUM_CP; i++) {
            const float bas = C[i] * t_pow * up[NUM_CP - 1 - i];
            t_pow *= tt;
            const float b2 = bas * bas;
            const float* m  = cp_means + (i * BATCH + b) * 2;   // warp-broadcast LDG
            const float* cv = cp_covs  + (i * BATCH + b) * 4;
            mx = fmaf(bas, m[0], mx);
            my = fmaf(bas, m[1], my);
            ca = fmaf(b2, cv[0], ca);
            cb = fmaf(b2, cv[1], cb);
            cc = fmaf(b2, cv[2], cc);
            cd = fmaf(b2, cv[3], cd);
        }
        const float det     = ca * cd - cb * cc;
        const float inv_det = 1.0f / det;
        const float HL2E    = 0.5f * 1.4426950408889634f;      // 0.5*log2(e)
        // exponent-space: s = c0*dx^2 + c1*dx*dy + c2*dy^2 + ls ; out = exp2(s)
        const float c0 = -HL2E * cd * inv_det;
        const float c1 =  HL2E * (cb + cc) * inv_det;
        const float c2 = -HL2E * ca * inv_det;
        const float ls = -0.5f * __log2f(39.478417604357434f * det);
        sP4[tp] = make_float4(mx, my, c0, c1);
        sP2[tp] = make_float2(c2, ls);
    }
    __syncthreads();

    const int w = tid >> 5;
    const int l = tid & 31;
    const float yl = (float)l;                       // lane-constant y values
    const float yh = yl + 32.0f;

    float* const out_base =
        out + ((size_t)b * MAP_W + (size_t)x0) * (MAP_H * MAP_T);

    for (int c = 0; c < X_PER_BLOCK; c++) {
        float* buf = tile[c & 1];
        float* bufl = buf + l * MAP_T;               // row y=l
        float* bufh = buf + (l + 32) * MAP_T;        // row y=l+32

        // Reuse-safety: buffer (c-2)'s bulk copy must be fully read.
        if (c >= 2) {
            if (tid == 0)
                asm volatile("cp.async.bulk.wait_group.read 1;" ::: "memory");
            __syncthreads();
        }

        const float xf = (float)(x0 + c);            // warp-uniform x

        for (int t = w; t < MAP_T; t += 8) {
            const float4 q4 = sP4[t];                // broadcast LDS
            const float2 q2 = sP2[t];
            // warp-uniform setup: s(y) = c2*y^2 + Bp*y + Cp
            const float dx   = xf - q4.x;
            const float cdx  = q4.w * dx;            // c1*dx
            const float K    = fmaf(q4.z * dx, dx, q2.y);      // c0*dx^2 + ls
            const float t2v  = fmaf(q2.x, q4.y, -cdx);         // c2*my - c1*dx
            const float Cp   = fmaf(q4.y, t2v, K);
            const float my2  = q4.y + q4.y;
            const float Bp   = fmaf(-q2.x, my2, cdx);          // c1*dx - 2*c2*my

            const float s0 = fmaf(fmaf(q2.x, yl, Bp), yl, Cp); // 2 FMA
            const float s1 = fmaf(fmaf(q2.x, yh, Bp), yh, Cp);
            bufl[t] = ex2(s0);                       // STS.32 (2-way conflict)
            bufh[t] = ex2(s1);
        }
        __syncthreads();

        // ---- issue async drain of chunk c (overlaps chunk c+1 compute) ----
        if (tid == 0) {
            asm volatile("fence.proxy.async;" ::: "memory");
            char* gdst = (char*)(out_base + (size_t)c * CHUNK_FLOATS);
            const unsigned ssrc = smem_u32(buf);
            asm volatile(
                "cp.async.bulk.global.shared::cta.bulk_group [%0], [%1], %2;"
                :: "l"(gdst), "r"(ssrc), "r"((unsigned)CHUNK_BYTES) : "memory");
            asm volatile("cp.async.bulk.commit_group;" ::: "memory");
        }
    }

    // SMEM must stay live until the engine finishes reading the last buffers.
    if (tid == 0)
        asm volatile("cp.async.bulk.wait_group.read 0;" ::: "memory");
}

extern "C" void kernel_launch(void* const* d_in, const int* in_sizes, int n_in,
                              void* d_out, int out_size)
{
    const float* cp_means = (const float*)d_in[0];  // (8,128,2)
    const float* cp_covs  = (const float*)d_in[1];  // (8,128,2,2)
    float* out = (float*)d_out;                     // (128,64,64,50)
    (void)in_sizes; (void)n_in; (void)out_size;

    probmap_kernel<<<NUM_BLOCKS, TPB>>>(cp_means, cp_covs, out);
}

// round 12
// speedup vs baseline: 1.0964x; 1.0553x over previous
#include <cuda_runtime.h>
#include <math.h>

// ProbabilisticMap: out[b][x][y][t] = N((x,y); mean(b,t), cov(b,t)) for a
// Bezier mixture of 8 control-point Gaussians.
// Shapes: cp_means (8,128,2), cp_covariances (8,128,2,2), out (128,64,64,50) fp32.
//
// R11: R10 Horner hot loop + perfect warp balance + single resident wave.
//   TPB=160 (5 warps): 50 t / 5 warps = exactly 10 iters per warp -> zero
//   barrier imbalance. Grid=1024 CTAs @ 8 CTAs/SM -> one fully-resident wave.
//   Block = one b x 8 x-slices; chunk = one x slice (64y x 50t = 12.8 KB,
//   contiguous in output), double-buffered cp.async.bulk drain.

#define MAP_W 64
#define MAP_H 64
#define MAP_T 50
#define NUM_CP 8
#define BATCH 128

#define TPB 160                                      // 5 warps
#define X_PER_BLOCK 8
#define CHUNK_FLOATS (MAP_H * MAP_T)                 // 3200 (one x slice)
#define CHUNK_BYTES  (CHUNK_FLOATS * 4)              // 12800
#define BLOCKS_PER_B (MAP_W / X_PER_BLOCK)           // 8
#define NUM_BLOCKS   (BATCH * BLOCKS_PER_B)          // 1024

__device__ __forceinline__ float ex2(float x) {
    float r;
    asm("ex2.approx.ftz.f32 %0, %1;" : "=f"(r) : "f"(x));
    return r;
}

__device__ __forceinline__ unsigned smem_u32(const void* p) {
    unsigned a;
    asm("{ .reg .u64 t; cvta.to.shared.u64 t, %1; cvt.u32.u64 %0, t; }"
        : "=r"(a) : "l"(p));
    return a;
}

__global__ __launch_bounds__(TPB)
void probmap_kernel(const float* __restrict__ cp_means,
                    const float* __restrict__ cp_covs,
                    float* __restrict__ out)
{
    __shared__ float4 sP4[MAP_T];                    // (mx, my, c0, c1)
    __shared__ float2 sP2[MAP_T];                    // (c2, ls)
    __shared__ __align__(16) float tile[2][CHUNK_FLOATS];  // 2 x 12.8 KB

    const int tid = threadIdx.x;
    const int b   = blockIdx.x >> 3;                 // 8 blocks per batch
    const int x0  = (blockIdx.x & 7) * X_PER_BLOCK;  // first x of this block

    // ---- Phase 0: per-t parameters (threads 0..49) ----
    if (tid < MAP_T) {
        const float tt = (float)tid * (1.0f / (float)(MAP_T - 1));
        const float u  = 1.0f - tt;
        const float C[NUM_CP] = {1.f, 7.f, 21.f, 35.f, 35.f, 21.f, 7.f, 1.f};

        float up[NUM_CP];
        up[0] = 1.0f;
#pragma unroll
        for (int i = 1; i < NUM_CP; i++) up[i] = up[i - 1] * u;

        float mx = 0.f, my = 0.f;
        float ca = 0.f, cb = 0.f, cc = 0.f, cd = 0.f;
        float t_pow = 1.0f;
#pragma unroll
        for (int i = 0; i < NUM_CP; i++) {
            const float bas = C[i] * t_pow * up[NUM_CP - 1 - i];
            t_pow *= tt;
            const float b2 = bas * bas;
            const float* m  = cp_means + (i * BATCH + b) * 2;   // warp-broadcast LDG
            const float* cv = cp_covs  + (i * BATCH + b) * 4;
            mx = fmaf(bas, m[0], mx);
            my = fmaf(bas, m[1], my);
            ca = fmaf(b2, cv[0], ca);
            cb = fmaf(b2, cv[1], cb);
            cc = fmaf(b2, cv[2], cc);
            cd = fmaf(b2, cv[3], cd);
        }
        const float det     = ca * cd - cb * cc;
        const float inv_det = 1.0f / det;
        const float HL2E    = 0.5f * 1.4426950408889634f;      // 0.5*log2(e)
        // exponent-space: s = c0*dx^2 + c1*dx*dy + c2*dy^2 + ls ; out = exp2(s)
        const float c0 = -HL2E * cd * inv_det;
        const float c1 =  HL2E * (cb + cc) * inv_det;
        const float c2 = -HL2E * ca * inv_det;
        const float ls = -0.5f * __log2f(39.478417604357434f * det);
        sP4[tid] = make_float4(mx, my, c0, c1);
        sP2[tid] = make_float2(c2, ls);
    }
    __syncthreads();

    const int w = tid >> 5;                          // 0..4
    const int l = tid & 31;
    const float yl = (float)l;                       // lane-constant y values
    const float yh = yl + 32.0f;

    float* const out_base =
        out + ((size_t)b * MAP_W + (size_t)x0) * (MAP_H * MAP_T);

    for (int c = 0; c < X_PER_BLOCK; c++) {
        float* buf = tile[c & 1];
        float* bufl = buf + l * MAP_T;               // row y=l
        float* bufh = buf + (l + 32) * MAP_T;        // row y=l+32

        // Reuse-safety: buffer (c-2)'s bulk copy must be fully read.
        if (c >= 2) {
            if (tid == 0)
                asm volatile("cp.async.bulk.wait_group.read 1;" ::: "memory");
            __syncthreads();
        }

        const float xf = (float)(x0 + c);            // warp-uniform x

        // 5 warps x stride-5: EXACTLY 10 iterations per warp (perfect balance).
#pragma unroll 2
        for (int t = w; t < MAP_T; t += 5) {
            const float4 q4 = sP4[t];                // broadcast LDS
            const float2 q2 = sP2[t];
            // warp-uniform setup: s(y) = c2*y^2 + Bp*y + Cp
            const float dx   = xf - q4.x;
            const float cdx  = q4.w * dx;            // c1*dx
            const float K    = fmaf(q4.z * dx, dx, q2.y);      // c0*dx^2 + ls
            const float t2v  = fmaf(q2.x, q4.y, -cdx);         // c2*my - c1*dx
            const float Cp   = fmaf(q4.y, t2v, K);
            const float my2  = q4.y + q4.y;
            const float Bp   = fmaf(-q2.x, my2, cdx);          // c1*dx - 2*c2*my

            const float s0 = fmaf(fmaf(q2.x, yl, Bp), yl, Cp); // 2 FMA
            const float s1 = fmaf(fmaf(q2.x, yh, Bp), yh, Cp);
            bufl[t] = ex2(s0);                       // STS.32 (2-way conflict)
            bufh[t] = ex2(s1);
        }
        __syncthreads();

        // ---- issue async drain of chunk c (overlaps chunk c+1 compute) ----
        if (tid == 0) {
            asm volatile("fence.proxy.async;" ::: "memory");
            char* gdst = (char*)(out_base + (size_t)c * CHUNK_FLOATS);
            const unsigned ssrc = smem_u32(buf);
            asm volatile(
                "cp.async.bulk.global.shared::cta.bulk_group [%0], [%1], %2;"
                :: "l"(gdst), "r"(ssrc), "r"((unsigned)CHUNK_BYTES) : "memory");
            asm volatile("cp.async.bulk.commit_group;" ::: "memory");
        }
    }

    // SMEM must stay live until the engine finishes reading the last buffers.
    if (tid == 0)
        asm volatile("cp.async.bulk.wait_group.read 0;" ::: "memory");
}

extern "C" void kernel_launch(void* const* d_in, const int* in_sizes, int n_in,
                              void* d_out, int out_size)
{
    const float* cp_means = (const float*)d_in[0];  // (8,128,2)
    const float* cp_covs  = (const float*)d_in[1];  // (8,128,2,2)
    float* out = (float*)d_out;                     // (128,64,64,50)
    (void)in_sizes; (void)n_in; (void)out_size;

    probmap_kernel<<<NUM_BLOCKS, TPB>>>(cp_means, cp_covs, out);
}

// round 13
// speedup vs baseline: 1.0992x; 1.0026x over previous
#include <cuda_runtime.h>
#include <math.h>

// ProbabilisticMap: out[b][x][y][t] = N((x,y); mean(b,t), cov(b,t)) for a
// Bezier mixture of 8 control-point Gaussians.
// Shapes: cp_means (8,128,2), cp_covariances (8,128,2,2), out (128,64,64,50) fp32.
//
// R12: conflict-free STS via half-warp t-split + finer CTA granularity.
//   Lanes 0-15 evaluate t0, lanes 16-31 evaluate t0+1; each lane covers
//   y = (l&15)+16k, k=0..3. STS bank = (18*yb + th + t0) mod 32 covers all 32
//   banks -> zero conflicts (R11 had a structural 2-way conflict: lanes l and
//   l+16 always collided at stride-50). 25 t-pairs / 5 warps = perfect balance.
//   X_PER_BLOCK=4 (2048 CTAs) halves wave-quantization tail.

#define MAP_W 64
#define MAP_H 64
#define MAP_T 50
#define NUM_CP 8
#define BATCH 128

#define TPB 160                                      // 5 warps
#define X_PER_BLOCK 4
#define CHUNK_FLOATS (MAP_H * MAP_T)                 // 3200 (one x slice)
#define CHUNK_BYTES  (CHUNK_FLOATS * 4)              // 12800
#define BLOCKS_PER_B (MAP_W / X_PER_BLOCK)           // 16
#define NUM_BLOCKS   (BATCH * BLOCKS_PER_B)          // 2048

__device__ __forceinline__ float ex2(float x) {
    float r;
    asm("ex2.approx.ftz.f32 %0, %1;" : "=f"(r) : "f"(x));
    return r;
}

__device__ __forceinline__ unsigned smem_u32(const void* p) {
    unsigned a;
    asm("{ .reg .u64 t; cvta.to.shared.u64 t, %1; cvt.u32.u64 %0, t; }"
        : "=r"(a) : "l"(p));
    return a;
}

__global__ __launch_bounds__(TPB)
void probmap_kernel(const float* __restrict__ cp_means,
                    const float* __restrict__ cp_covs,
                    float* __restrict__ out)
{
    __shared__ float4 sP4[MAP_T];                    // (mx, my, c0, c1)
    __shared__ float2 sP2[MAP_T];                    // (c2, ls)
    __shared__ __align__(16) float tile[2][CHUNK_FLOATS];  // 2 x 12.8 KB

    const int tid = threadIdx.x;
    const int b   = blockIdx.x >> 4;                 // 16 blocks per batch
    const int x0  = (blockIdx.x & 15) * X_PER_BLOCK; // first x of this block

    // ---- Phase 0: per-t parameters (threads 0..49) ----
    if (tid < MAP_T) {
        const float tt = (float)tid * (1.0f / (float)(MAP_T - 1));
        const float u  = 1.0f - tt;
        const float C[NUM_CP] = {1.f, 7.f, 21.f, 35.f, 35.f, 21.f, 7.f, 1.f};

        float up[NUM_CP];
        up[0] = 1.0f;
#pragma unroll
        for (int i = 1; i < NUM_CP; i++) up[i] = up[i - 1] * u;

        float mx = 0.f, my = 0.f;
        float ca = 0.f, cb = 0.f, cc = 0.f, cd = 0.f;
        float t_pow = 1.0f;
#pragma unroll
        for (int i = 0; i < NUM_CP; i++) {
            const float bas = C[i] * t_pow * up[NUM_CP - 1 - i];
            t_pow *= tt;
            const float b2 = bas * bas;
            const float* m  = cp_means + (i * BATCH + b) * 2;   // warp-broadcast LDG
            const float* cv = cp_covs  + (i * BATCH + b) * 4;
            mx = fmaf(bas, m[0], mx);
            my = fmaf(bas, m[1], my);
            ca = fmaf(b2, cv[0], ca);
            cb = fmaf(b2, cv[1], cb);
            cc = fmaf(b2, cv[2], cc);
            cd = fmaf(b2, cv[3], cd);
        }
        const float det     = ca * cd - cb * cc;
        const float inv_det = 1.0f / det;
        const float HL2E    = 0.5f * 1.4426950408889634f;      // 0.5*log2(e)
        // exponent-space: s = c0*dx^2 + c1*dx*dy + c2*dy^2 + ls ; out = exp2(s)
        const float c0 = -HL2E * cd * inv_det;
        const float c1 =  HL2E * (cb + cc) * inv_det;
        const float c2 = -HL2E * ca * inv_det;
        const float ls = -0.5f * __log2f(39.478417604357434f * det);
        sP4[tid] = make_float4(mx, my, c0, c1);
        sP2[tid] = make_float2(c2, ls);
    }
    __syncthreads();

    const int w  = tid >> 5;                         // warp 0..4
    const int l  = tid & 31;
    const int th = l >> 4;                           // 0: t0, 1: t0+1
    const int yb = l & 15;                           // base y (0..15)
    const float ybf = (float)yb;

    float* const out_base =
        out + ((size_t)b * MAP_W + (size_t)x0) * (MAP_H * MAP_T);

    for (int c = 0; c < X_PER_BLOCK; c++) {
        float* buf = tile[c & 1];

        // Reuse-safety: buffer (c-2)'s bulk copy must be fully read.
        if (c >= 2) {
            if (tid == 0)
                asm volatile("cp.async.bulk.wait_group.read 1;" ::: "memory");
            __syncthreads();
        }

        const float xf = (float)(x0 + c);            // warp-uniform x

        // 25 t-pairs over 5 warps: warp w takes pairs w*5 .. w*5+4.
#pragma unroll
        for (int i = 0; i < 5; i++) {
            const int t = 2 * (w * 5 + i) + th;      // lane's t (2 per warp)
            const float4 q4 = sP4[t];                // 2 distinct addrs -> no conflict
            const float2 q2 = sP2[t];
            // s(y) = c2*y^2 + Bp*y + Cp  (per-lane setup, amortized over 4 y)
            const float dx  = xf - q4.x;
            const float cdx = q4.w * dx;                       // c1*dx
            const float K   = fmaf(q4.z * dx, dx, q2.y);       // c0*dx^2 + ls
            const float t2v = fmaf(q2.x, q4.y, -cdx);          // c2*my - c1*dx
            const float Cp  = fmaf(q4.y, t2v, K);
            const float Bp  = fmaf(-q2.x, q4.y + q4.y, cdx);   // c1*dx - 2*c2*my

            float* dst = buf + yb * MAP_T + t;
#pragma unroll
            for (int k = 0; k < 4; k++) {            // y = yb + 16k
                const float yv = ybf + 16.0f * (float)k;
                const float s  = fmaf(fmaf(q2.x, yv, Bp), yv, Cp);
                dst[k * 16 * MAP_T] = ex2(s);        // STS.32, conflict-free
            }
        }
        __syncthreads();

        // ---- issue async drain of chunk c (overlaps chunk c+1 compute) ----
        if (tid == 0) {
            asm volatile("fence.proxy.async;" ::: "memory");
            char* gdst = (char*)(out_base + (size_t)c * CHUNK_FLOATS);
            const unsigned ssrc = smem_u32(buf);
            asm volatile(
                "cp.async.bulk.global.shared::cta.bulk_group [%0], [%1], %2;"
                :: "l"(gdst), "r"(ssrc), "r"((unsigned)CHUNK_BYTES) : "memory");
            asm volatile("cp.async.bulk.commit_group;" ::: "memory");
        }
    }

    // SMEM must stay live until the engine finishes reading the last buffers.
    if (tid == 0)
        asm volatile("cp.async.bulk.wait_group.read 0;" ::: "memory");
}

extern "C" void kernel_launch(void* const* d_in, const int* in_sizes, int n_in,
                              void* d_out, int out_size)
{
    const float* cp_means = (const float*)d_in[0];  // (8,128,2)
    const float* cp_covs  = (const float*)d_in[1];  // (8,128,2,2)
    float* out = (float*)d_out;                     // (128,64,64,50)
    (void)in_sizes; (void)n_in; (void)out_size;

    probmap_kernel<<<NUM_BLOCKS, TPB>>>(cp_means, cp_covs, out);
}

// round 14
// speedup vs baseline: 1.1107x; 1.0104x over previous
#include <cuda_runtime.h>
#include <math.h>

// ProbabilisticMap: out[b][x][y][t] = N((x,y); mean(b,t), cov(b,t)) for a
// Bezier mixture of 8 control-point Gaussians.
// Shapes: cp_means (8,128,2), cp_covariances (8,128,2,2), out (128,64,64,50) fp32.
//
// R13: no SMEM tile, no barriers, no bulk engine.
//   Lane l (<25) owns t = 2l, 2l+1 with all 6 coefficients per t in REGISTERS
//   (loaded once from the phase-0 smem params). For each (x,y) pixel the lane
//   evaluates its two t's by Horner-in-y (2 FMA each, exact) + ex2, and the
//   warp stores one contiguous 200 B run (float2 per lane) directly to GMEM.
//   Successive y iterations are contiguous -> perfectly sequential store
//   stream. Hot loop: 4 FMA + 2 EX2 + 1 STG.64 + induction per 50 elements.

#define MAP_W 64
#define MAP_H 64
#define MAP_T 50
#define NUM_CP 8
#define BATCH 128

#define TPB 128                                      // 4 warps
#define X_PER_WARP 2
#define X_PER_BLOCK (4 * X_PER_WARP)                 // 8
#define BLOCKS_PER_B (MAP_W / X_PER_BLOCK)           // 8
#define NUM_BLOCKS   (BATCH * BLOCKS_PER_B)          // 1024

__device__ __forceinline__ float ex2(float x) {
    float r;
    asm("ex2.approx.ftz.f32 %0, %1;" : "=f"(r) : "f"(x));
    return r;
}

__global__ __launch_bounds__(TPB)
void probmap_kernel(const float* __restrict__ cp_means,
                    const float* __restrict__ cp_covs,
                    float* __restrict__ out)
{
    __shared__ float4 sP4[MAP_T];                    // (mx, my, c0, c1)
    __shared__ float2 sP2[MAP_T];                    // (c2, ls)

    const int tid = threadIdx.x;
    const int b   = blockIdx.x >> 3;                 // 8 blocks per batch
    const int x0  = (blockIdx.x & 7) * X_PER_BLOCK;  // first x of this block

    // ---- Phase 0: per-t parameters (threads 0..49) ----
    if (tid < MAP_T) {
        const float tt = (float)tid * (1.0f / (float)(MAP_T - 1));
        const float u  = 1.0f - tt;
        const float C[NUM_CP] = {1.f, 7.f, 21.f, 35.f, 35.f, 21.f, 7.f, 1.f};

        float up[NUM_CP];
        up[0] = 1.0f;
#pragma unroll
        for (int i = 1; i < NUM_CP; i++) up[i] = up[i - 1] * u;

        float mx = 0.f, my = 0.f;
        float ca = 0.f, cb = 0.f, cc = 0.f, cd = 0.f;
        float t_pow = 1.0f;
#pragma unroll
        for (int i = 0; i < NUM_CP; i++) {
            const float bas = C[i] * t_pow * up[NUM_CP - 1 - i];
            t_pow *= tt;
            const float b2 = bas * bas;
            const float* m  = cp_means + (i * BATCH + b) * 2;   // warp-broadcast LDG
            const float* cv = cp_covs  + (i * BATCH + b) * 4;
            mx = fmaf(bas, m[0], mx);
            my = fmaf(bas, m[1], my);
            ca = fmaf(b2, cv[0], ca);
            cb = fmaf(b2, cv[1], cb);
            cc = fmaf(b2, cv[2], cc);
            cd = fmaf(b2, cv[3], cd);
        }
        const float det     = ca * cd - cb * cc;
        const float inv_det = 1.0f / det;
        const float HL2E    = 0.5f * 1.4426950408889634f;      // 0.5*log2(e)
        // exponent-space: s = c0*dx^2 + c1*dx*dy + c2*dy^2 + ls ; out = exp2(s)
        const float c0 = -HL2E * cd * inv_det;
        const float c1 =  HL2E * (cb + cc) * inv_det;
        const float c2 = -HL2E * ca * inv_det;
        const float ls = -0.5f * __log2f(39.478417604357434f * det);
        sP4[tid] = make_float4(mx, my, c0, c1);
        sP2[tid] = make_float2(c2, ls);
    }
    __syncthreads();                                 // the ONLY barrier

    const int w = tid >> 5;                          // warp 0..3
    const int l = tid & 31;
    const bool valid = (l < 25);
    const int tA = valid ? 2 * l : 0;                // lane's t-pair (clamped)

    // Coefficients live in registers for the whole kernel.
    const float4 a4 = sP4[tA];     const float2 a2 = sP2[tA];
    const float4 b4 = sP4[tA + 1]; const float2 b2 = sP2[tA + 1];

    const int xw = x0 + w * X_PER_WARP;              // warp's first x

#pragma unroll
    for (int xi = 0; xi < X_PER_WARP; xi++) {
        const int   x  = xw + xi;
        const float xf = (float)x;

        // Per-(t,x) Horner coefficients: s(y) = c2*y^2 + Bp*y + Cp  (amortized over 64 y)
        const float dxA  = xf - a4.x;
        const float cdxA = a4.w * dxA;
        const float CpA  = fmaf(a4.y, fmaf(a2.x, a4.y, -cdxA),
                                fmaf(a4.z * dxA, dxA, a2.y));
        const float BpA  = fmaf(-a2.x, a4.y + a4.y, cdxA);

        const float dxB  = xf - b4.x;
        const float cdxB = b4.w * dxB;
        const float CpB  = fmaf(b4.y, fmaf(b2.x, b4.y, -cdxB),
                                fmaf(b4.z * dxB, dxB, b2.y));
        const float BpB  = fmaf(-b2.x, b4.y + b4.y, cdxB);

        // Lane writes out[b][x][y][2l..2l+1]; warp covers 200 contiguous bytes
        // per y, and y-steps are contiguous -> sequential store stream.
        float* op = out + (((size_t)b * MAP_W + x) * MAP_H) * MAP_T + tA;

        float yf = 0.0f;
#pragma unroll 4
        for (int y = 0; y < MAP_H; y++) {
            const float s0 = fmaf(fmaf(a2.x, yf, BpA), yf, CpA);  // 2 FMA
            const float s1 = fmaf(fmaf(b2.x, yf, BpB), yf, CpB);  // 2 FMA
            float2 r;
            r.x = ex2(s0);
            r.y = ex2(s1);
            if (valid) __stcs((float2*)op, r);       // STG.64, streaming
            op += MAP_T;
            yf += 1.0f;
        }
    }
}

extern "C" void kernel_launch(void* const* d_in, const int* in_sizes, int n_in,
                              void* d_out, int out_size)
{
    const float* cp_means = (const float*)d_in[0];  // (8,128,2)
    const float* cp_covs  = (const float*)d_in[1];  // (8,128,2,2)
    float* out = (float*)d_out;                     // (128,64,64,50)
    (void)in_sizes; (void)n_in; (void)out_size;

    probmap_kernel<<<NUM_BLOCKS, TPB>>>(cp_means, cp_covs, out);
}

// round 15
// speedup vs baseline: 1.2116x; 1.0909x over previous
#include <cuda_runtime.h>
#include <math.h>

// ProbabilisticMap: out[b][x][y][t] = N((x,y); mean(b,t), cov(b,t)) for a
// Bezier mixture of 8 control-point Gaussians.
// Shapes: cp_means (8,128,2), cp_covariances (8,128,2,2), out (128,64,64,50) fp32.
//
// R14: R13 dataflow (register-resident t-pair coefficients, Horner-in-y,
// direct contiguous STG.64 stream, zero tiles/barriers) with 2x the warps:
//   TPB=256, 8 warps, each warp owns ONE x-slice (64 y-iterations).
//   R13 ran ~28 warps/SM at issue=30% (latency-starved); this doubles
//   latency-hiding capacity and halves each thread's serial chain.

#define MAP_W 64
#define MAP_H 64
#define MAP_T 50
#define NUM_CP 8
#define BATCH 128

#define TPB 256                                      // 8 warps
#define X_PER_BLOCK 8                                // one x per warp
#define BLOCKS_PER_B (MAP_W / X_PER_BLOCK)           // 8
#define NUM_BLOCKS   (BATCH * BLOCKS_PER_B)          // 1024

__device__ __forceinline__ float ex2(float x) {
    float r;
    asm("ex2.approx.ftz.f32 %0, %1;" : "=f"(r) : "f"(x));
    return r;
}

__global__ __launch_bounds__(TPB)
void probmap_kernel(const float* __restrict__ cp_means,
                    const float* __restrict__ cp_covs,
                    float* __restrict__ out)
{
    __shared__ float4 sP4[MAP_T];                    // (mx, my, c0, c1)
    __shared__ float2 sP2[MAP_T];                    // (c2, ls)

    const int tid = threadIdx.x;
    const int b   = blockIdx.x >> 3;                 // 8 blocks per batch
    const int x0  = (blockIdx.x & 7) * X_PER_BLOCK;  // first x of this block

    // ---- Phase 0: per-t parameters (threads 0..49) ----
    if (tid < MAP_T) {
        const float tt = (float)tid * (1.0f / (float)(MAP_T - 1));
        const float u  = 1.0f - tt;
        const float C[NUM_CP] = {1.f, 7.f, 21.f, 35.f, 35.f, 21.f, 7.f, 1.f};

        float up[NUM_CP];
        up[0] = 1.0f;
#pragma unroll
        for (int i = 1; i < NUM_CP; i++) up[i] = up[i - 1] * u;

        float mx = 0.f, my = 0.f;
        float ca = 0.f, cb = 0.f, cc = 0.f, cd = 0.f;
        float t_pow = 1.0f;
#pragma unroll
        for (int i = 0; i < NUM_CP; i++) {
            const float bas = C[i] * t_pow * up[NUM_CP - 1 - i];
            t_pow *= tt;
            const float b2 = bas * bas;
            const float* m  = cp_means + (i * BATCH + b) * 2;   // warp-broadcast LDG
            const float* cv = cp_covs  + (i * BATCH + b) * 4;
            mx = fmaf(bas, m[0], mx);
            my = fmaf(bas, m[1], my);
            ca = fmaf(b2, cv[0], ca);
            cb = fmaf(b2, cv[1], cb);
            cc = fmaf(b2, cv[2], cc);
            cd = fmaf(b2, cv[3], cd);
        }
        const float det     = ca * cd - cb * cc;
        const float inv_det = 1.0f / det;
        const float HL2E    = 0.5f * 1.4426950408889634f;      // 0.5*log2(e)
        // exponent-space: s = c0*dx^2 + c1*dx*dy + c2*dy^2 + ls ; out = exp2(s)
        const float c0 = -HL2E * cd * inv_det;
        const float c1 =  HL2E * (cb + cc) * inv_det;
        const float c2 = -HL2E * ca * inv_det;
        const float ls = -0.5f * __log2f(39.478417604357434f * det);
        sP4[tid] = make_float4(mx, my, c0, c1);
        sP2[tid] = make_float2(c2, ls);
    }
    __syncthreads();                                 // the ONLY barrier

    const int w = tid >> 5;                          // warp 0..7
    const int l = tid & 31;
    const bool valid = (l < 25);
    const int tA = valid ? 2 * l : 0;                // lane's t-pair (clamped)

    // Coefficients live in registers for the whole kernel.
    const float4 a4 = sP4[tA];     const float2 a2 = sP2[tA];
    const float4 b4 = sP4[tA + 1]; const float2 b2 = sP2[tA + 1];

    const int   x  = x0 + w;                         // warp's x-slice
    const float xf = (float)x;

    // Per-(t,x) Horner coefficients: s(y) = c2*y^2 + Bp*y + Cp (amortized over 64 y)
    const float dxA  = xf - a4.x;
    const float cdxA = a4.w * dxA;
    const float CpA  = fmaf(a4.y, fmaf(a2.x, a4.y, -cdxA),
                            fmaf(a4.z * dxA, dxA, a2.y));
    const float BpA  = fmaf(-a2.x, a4.y + a4.y, cdxA);

    const float dxB  = xf - b4.x;
    const float cdxB = b4.w * dxB;
    const float CpB  = fmaf(b4.y, fmaf(b2.x, b4.y, -cdxB),
                            fmaf(b4.z * dxB, dxB, b2.y));
    const float BpB  = fmaf(-b2.x, b4.y + b4.y, cdxB);

    // Lane writes out[b][x][y][2l..2l+1]; warp covers 200 contiguous bytes per
    // y, and y-steps are contiguous -> perfectly sequential store stream.
    float* op = out + (((size_t)b * MAP_W + x) * MAP_H) * MAP_T + tA;

#pragma unroll 8
    for (int y = 0; y < MAP_H; y++) {
        const float yf = (float)y;                   // no serial induction dep
        const float s0 = fmaf(fmaf(a2.x, yf, BpA), yf, CpA);  // 2 FMA
        const float s1 = fmaf(fmaf(b2.x, yf, BpB), yf, CpB);  // 2 FMA
        float2 r;
        r.x = ex2(s0);
        r.y = ex2(s1);
        if (valid) __stcs((float2*)(op + (size_t)y * MAP_T), r);  // STG.64
    }
}

extern "C" void kernel_launch(void* const* d_in, const int* in_sizes, int n_in,
                              void* d_out, int out_size)
{
    const float* cp_means = (const float*)d_in[0];  // (8,128,2)
    const float* cp_covs  = (const float*)d_in[1];  // (8,128,2,2)
    float* out = (float*)d_out;                     // (128,64,64,50)
    (void)in_sizes; (void)n_in; (void)out_size;

    probmap_kernel<<<NUM_BLOCKS, TPB>>>(cp_means, cp_covs, out);
}